// round 14
// baseline (speedup 1.0000x reference)
#include <cuda_runtime.h>
#include <cuda_fp16.h>
#include <mma.h>
#include <cstdint>

using namespace nvcuda;

typedef unsigned long long u64;

// ---------------- packed f32x2 helpers ----------------
__device__ __forceinline__ u64 pk2(float a, float b) {
    u64 r; asm("mov.b64 %0, {%1,%2};" : "=l"(r) : "f"(a), "f"(b)); return r;
}
__device__ __forceinline__ void upk2(u64 v, float& a, float& b) {
    asm("mov.b64 {%0,%1}, %2;" : "=f"(a), "=f"(b) : "l"(v));
}
__device__ __forceinline__ u64 ffma2(u64 a, u64 b, u64 c) {
    u64 d; asm("fma.rn.f32x2 %0, %1, %2, %3;" : "=l"(d) : "l"(a), "l"(b), "l"(c)); return d;
}
__device__ __forceinline__ u64 fadd2(u64 a, u64 b) {
    u64 d; asm("add.rn.f32x2 %0, %1, %2;" : "=l"(d) : "l"(a), "l"(b)); return d;
}
__device__ __forceinline__ float tanh_(float x) {
    float t; asm("tanh.approx.f32 %0, %1;" : "=f"(t) : "f"(x)); return t;
}

#define H     1024
#define DIN   784
#define DOUT  10
#define MAXB  16384
#define KPAD2 800          // 25 * 32; zero-init padding beyond 784
#define NI    25           // GEMM outer iterations (K-step 32)

__device__ float g_xW1[(size_t)MAXB * H];                        // x @ W1 (fp32)
__device__ __align__(16) __half g_xh[(size_t)MAXB * KPAD2];      // x  fp16 [m][k], zero-pad
__device__ __align__(16) __half g_w1h[(size_t)KPAD2 * H];        // W1 fp16 [k][n], zero-pad

// ==================== merged conv kernel: fp32 -> fp16 (one-time) ====================
__global__ __launch_bounds__(256) void conv_all(const float* __restrict__ x,
                                                const float* __restrict__ W1, int B) {
    int u = blockIdx.x * 256 + threadIdx.x;
    const int xunits = B * (KPAD2 / 8);
    const int wunits = KPAD2 * (H / 8);
    if (u < xunits) {
        int m = u / (KPAD2 / 8), k = (u - m * (KPAD2 / 8)) * 8;
        ushort h[8];
#pragma unroll
        for (int i = 0; i < 8; ++i)
            h[i] = (k + i < DIN)
                 ? __half_as_ushort(__float2half_rn(x[(size_t)m * DIN + k + i]))
                 : (ushort)0;
        *(ushort4*)(g_xh + (size_t)m * KPAD2 + k)     = make_ushort4(h[0], h[1], h[2], h[3]);
        *(ushort4*)(g_xh + (size_t)m * KPAD2 + k + 4) = make_ushort4(h[4], h[5], h[6], h[7]);
    } else if (u < xunits + wunits) {
        int v = u - xunits;
        int k = v / (H / 8), n = (v - k * (H / 8)) * 8;
        ushort h[8];
#pragma unroll
        for (int i = 0; i < 8; ++i)
            h[i] = (k < DIN)
                 ? __half_as_ushort(__float2half_rn(W1[(size_t)k * H + n + i]))
                 : (ushort)0;
        *(ushort4*)(g_w1h + (size_t)k * H + n)     = make_ushort4(h[0], h[1], h[2], h[3]);
        *(ushort4*)(g_w1h + (size_t)k * H + n + 4) = make_ushort4(h[4], h[5], h[6], h[7]);
    }
}

// ==================== fp16 MMA GEMM, K-step 32, cp.async 3-stage ring ====================
// CTA tile 128x128. A stride 40 elems (80B rows), B stride 136 (272B rows) — both
// conflict-free for ldmatrix. 25 iters, 1 barrier each, wait_group 1 keeps one
// cp.async group in flight through the compute body. Dynamic smem (56.8 KB).
#define ASTR 40
#define BSTR2 136
#define ATILE (128 * ASTR)
#define BTILE (32 * BSTR2)
#define MMA3_BYTES (3 * (ATILE + BTILE) * 2)   // 56832

__device__ __forceinline__ void cp16(uint32_t dst, const void* src) {
    asm volatile("cp.async.cg.shared.global [%0], [%1], 16;" :: "r"(dst), "l"(src));
}

__global__ __launch_bounds__(256, 2) void mma_xw1() {
    extern __shared__ __half gsm[];
    __half* sA = gsm;                 // [3][ATILE]
    __half* sB = gsm + 3 * ATILE;     // [3][BTILE]

    const int tid  = threadIdx.x;
    const int warp = tid >> 5;
    const int m0 = blockIdx.y * 128;
    const int n0 = blockIdx.x * 128;
    const int wm = (warp >> 2) * 64;
    const int wn = (warp & 3) * 32;

    wmma::fragment<wmma::accumulator, 16, 16, 16, float> acc[4][2];
#pragma unroll
    for (int i = 0; i < 4; ++i)
#pragma unroll
        for (int j = 0; j < 2; ++j) wmma::fill_fragment(acc[i][j], 0.0f);

    const int arow = tid >> 1, ak = (tid & 1) * 16;
    const __half* asrc = g_xh + (size_t)(m0 + arow) * KPAD2 + ak;
    const int aoff = arow * ASTR + ak;
    const int bkr = tid >> 3, bnc = (tid & 7) * 16;
    const __half* bsrc = g_w1h + (size_t)bkr * H + n0 + bnc;
    const int boff = bkr * BSTR2 + bnc;

    auto cpAB = [&](int it, int s) {
        __half* a = sA + s * ATILE;
        __half* b = sB + s * BTILE;
        cp16((uint32_t)__cvta_generic_to_shared(a + aoff),     asrc + it * 32);
        cp16((uint32_t)__cvta_generic_to_shared(a + aoff + 8), asrc + it * 32 + 8);
        cp16((uint32_t)__cvta_generic_to_shared(b + boff),     bsrc + (size_t)it * 32 * H);
        cp16((uint32_t)__cvta_generic_to_shared(b + boff + 8), bsrc + (size_t)it * 32 * H + 8);
        asm volatile("cp.async.commit_group;" ::: "memory");
    };

    cpAB(0, 0);
    cpAB(1, 1);

    for (int it = 0; it < NI; ++it) {
        if (it + 1 < NI) { asm volatile("cp.async.wait_group 1;" ::: "memory"); }
        else             { asm volatile("cp.async.wait_group 0;" ::: "memory"); }
        __syncthreads();                       // stage it%3 full CTA-wide; stage (it+2)%3 reads done
        if (it + 2 < NI) cpAB(it + 2, (it + 2) % 3);

        const int s = it % 3;
        const __half* a = sA + s * ATILE;
        const __half* b = sB + s * BTILE;
#pragma unroll
        for (int ks = 0; ks < 32; ks += 16) {
            wmma::fragment<wmma::matrix_b, 16, 16, 16, __half, wmma::row_major> bf[2];
#pragma unroll
            for (int j = 0; j < 2; ++j)
                wmma::load_matrix_sync(bf[j], &b[ks * BSTR2 + wn + j * 16], BSTR2);
#pragma unroll
            for (int i = 0; i < 4; ++i) {
                wmma::fragment<wmma::matrix_a, 16, 16, 16, __half, wmma::row_major> af;
                wmma::load_matrix_sync(af, &a[(wm + i * 16) * ASTR + ks], ASTR);
#pragma unroll
                for (int j = 0; j < 2; ++j)
                    wmma::mma_sync(acc[i][j], af, bf[j], acc[i][j]);
            }
        }
    }

#pragma unroll
    for (int i = 0; i < 4; ++i)
#pragma unroll
        for (int j = 0; j < 2; ++j) {
            float* C = g_xW1 + (size_t)(m0 + wm + i * 16) * H + (n0 + wn + j * 16);
            wmma::store_matrix_sync(C, acc[i][j], H, wmma::mem_row_major);
        }
}

// ==================== Kernel 2: 50-step settle (R5 skeleton, micro-diet) ====================
// Diffs vs R5: (1) c1 folded into p-dot accumulator init via pk2(c1,0) — moves
// one FADD/element off the fma pipe; (2) wpart stride 34 (16B rows) + phase-B
// reads via LDS.128. Everything else identical.
#define WST 34

__global__ __launch_bounds__(256, 2) void settle_kernel(
    const float* __restrict__ u1g, const float* __restrict__ u2g,
    const float* __restrict__ W2g, const float* __restrict__ b1g,
    const float* __restrict__ b2g, const int* __restrict__ steps_p,
    float* __restrict__ outg)
{
    __shared__ float c1_s[4 * H];
    __shared__ __align__(16) float r2_s[4][12];
    __shared__ __align__(16) u64 wpart[80 * WST];

    const int tid  = threadIdx.x;
    const int lane = tid & 31;
    const int wid  = tid >> 5;
    const int b0   = blockIdx.x * 4;
    const int nsteps = *steps_p;

    u64 w2p[4][5];
#pragma unroll
    for (int j = 0; j < 4; ++j) {
        const float* w = W2g + (tid + 256 * j) * DOUT;
#pragma unroll
        for (int k = 0; k < 5; ++k)
            w2p[j][k] = pk2(w[2 * k] * 0.0625f, w[2 * k + 1] * 0.0625f);
    }

    float u1v[4][4];
#pragma unroll
    for (int r = 0; r < 4; ++r)
#pragma unroll
        for (int j = 0; j < 4; ++j)
            u1v[r][j] = 0.5f * u1g[(size_t)(b0 + r) * H + tid + 256 * j];

    {
        const float4* xs = (const float4*)(g_xW1 + (size_t)b0 * H);
        const float4* bs = (const float4*)b1g;
        float4* dst = (float4*)c1_s;
#pragma unroll
        for (int i = 0; i < 4; ++i) {
            int e = tid + 256 * i;
            float4 xv = xs[e];
            float4 bv = bs[e & 255];
            dst[e] = make_float4(fmaf(0.03125f, xv.x, 0.0625f * bv.x),
                                 fmaf(0.03125f, xv.y, 0.0625f * bv.y),
                                 fmaf(0.03125f, xv.z, 0.0625f * bv.z),
                                 fmaf(0.03125f, xv.w, 0.0625f * bv.w));
        }
    }

    const bool pb = tid < 160;
    const int r_b  = tid / 40;
    const int rem  = tid - 40 * r_b;
    const int o_b  = rem >> 2;
    const int q4   = rem & 3;
    const int k_b  = o_b >> 1;
    const int half = o_b & 1;
    const float* fb = (const float*)(wpart + ((size_t)((r_b * 5 + k_b) * 4 + q4)) * WST);
    const float* fb_pre = (const float*)(wpart + ((size_t)(k_b * 4 + q4)) * WST);

    {
        u64 qa[5];
#pragma unroll
        for (int k = 0; k < 5; ++k)
            qa[k] = fadd2(fadd2(w2p[0][k], w2p[1][k]), fadd2(w2p[2][k], w2p[3][k]));
#pragma unroll
        for (int k = 0; k < 5; ++k)
            qa[k] = fadd2(qa[k], __shfl_xor_sync(0xffffffffu, qa[k], 16));
        if (lane < 16) {
            int pIdx = wid * 16 + lane;
            int chunk = pIdx >> 5, pos = pIdx & 31;
#pragma unroll
            for (int k = 0; k < 5; ++k)
                wpart[(k * 4 + chunk) * WST + pos] = qa[k];
        }
    }
    __syncthreads();

    float C2v = 0.0f, wv = 0.0f, r2v = 0.0f;
    if (pb) {
        float s0 = 0, s1 = 0, s2 = 0, s3 = 0;
#pragma unroll
        for (int i = 0; i < 16; ++i) {
            float4 z = *(const float4*)(fb_pre + 4 * i);
            s0 += z.x; s1 += z.y; s2 += z.z; s3 += z.w;
        }
        float s = half ? (s1 + s3) : (s0 + s2);
        s += __shfl_xor_sync(0xffffffffu, s, 1);
        s += __shfl_xor_sync(0xffffffffu, s, 2);
        C2v = fmaf(8.0f, s, b2g[o_b]);
        wv  = 0.5f * u2g[(b0 + r_b) * DOUT + o_b];
        float tau = tanh_(wv);
        r2v = fmaf(0.5f, tau, 0.5f);
        if (q4 == 0) r2_s[r_b][o_b] = r2v;
    }
    __syncthreads();

    for (int s = 0; s < nsteps; ++s) {
#pragma unroll
        for (int r = 0; r < 4; ++r) {
            ulonglong2 ra = *(const ulonglong2*)&r2_s[r][0];
            ulonglong2 rb = *(const ulonglong2*)&r2_s[r][4];
            u64 rc = *(const u64*)&r2_s[r][8];
            u64 r2p[5] = {ra.x, ra.y, rb.x, rb.y, rc};
            u64 qacc[5] = {0ULL, 0ULL, 0ULL, 0ULL, 0ULL};
#pragma unroll
            for (int j = 0; j < 4; ++j) {
                float c1v = c1_s[r * H + tid + 256 * j];
                float v  = u1v[r][j];
                float th = tanh_(v);
                u64 p2 = ffma2(w2p[j][0], r2p[0], pk2(c1v, 0.0f));
                p2 = ffma2(w2p[j][1], r2p[1], p2);
                p2 = ffma2(w2p[j][2], r2p[2], p2);
                p2 = ffma2(w2p[j][3], r2p[3], p2);
                p2 = ffma2(w2p[j][4], r2p[4], p2);
                float pa, pb2; upk2(p2, pa, pb2);
                u64 th2 = pk2(th, th);
#pragma unroll
                for (int k = 0; k < 5; ++k) qacc[k] = ffma2(th2, w2p[j][k], qacc[k]);
                float t   = pa + pb2;
                float omt = fmaf(-th, th, 1.0f);
                u1v[r][j] = fmaf(omt, t, 0.5f * v);
            }
#pragma unroll
            for (int k = 0; k < 5; ++k)
                qacc[k] = fadd2(qacc[k], __shfl_xor_sync(0xffffffffu, qacc[k], 16));
            if (lane < 16) {
                int pIdx = wid * 16 + lane;
                int chunk = pIdx >> 5, pos = pIdx & 31;
#pragma unroll
                for (int k = 0; k < 5; ++k)
                    wpart[((r * 5 + k) * 4 + chunk) * WST + pos] = qacc[k];
            }
        }
        __syncthreads();

        if (pb) {
            float s0 = 0, s1 = 0, s2 = 0, s3 = 0;
#pragma unroll
            for (int i = 0; i < 16; ++i) {
                float4 z = *(const float4*)(fb + 4 * i);
                s0 += z.x; s1 += z.y; s2 += z.z; s3 += z.w;
            }
            float sv = half ? (s1 + s3) : (s0 + s2);
            sv += __shfl_xor_sync(0xffffffffu, sv, 1);
            sv += __shfl_xor_sync(0xffffffffu, sv, 2);
            float gq  = fmaf(8.0f, sv, C2v);
            float tau = tanh_(wv);
            float om  = fmaf(-tau, tau, 1.0f);
            wv = fmaf(0.0625f * om, gq, 0.5f * wv);
            r2v = fmaf(0.5f, tanh_(wv), 0.5f);
            if (q4 == 0) r2_s[r_b][o_b] = r2v;
        }
        __syncthreads();
    }

    if (pb && q4 == 0)
        outg[(b0 + r_b) * DOUT + o_b] = r2v;
}

// ==================== launch ====================
extern "C" void kernel_launch(void* const* d_in, const int* in_sizes, int n_in,
                              void* d_out, int out_size) {
    const float* x     = (const float*)d_in[0];
    const float* u1    = (const float*)d_in[1];
    const float* u2    = (const float*)d_in[2];
    const float* W1    = (const float*)d_in[3];
    const float* W2    = (const float*)d_in[4];
    const float* b1    = (const float*)d_in[5];
    const float* b2    = (const float*)d_in[6];
    const int*   steps = (const int*)d_in[7];
    float* out = (float*)d_out;

    const int B = in_sizes[1] / H;

    cudaFuncSetAttribute(mma_xw1, cudaFuncAttributeMaxDynamicSharedMemorySize,
                         MMA3_BYTES);

    const int cunits = B * (KPAD2 / 8) + KPAD2 * (H / 8);
    conv_all<<<(cunits + 255) / 256, 256>>>(x, W1, B);
    mma_xw1<<<dim3(H / 128, B / 128), 256, MMA3_BYTES>>>();
    settle_kernel<<<B / 4, 256>>>(u1, u2, W2, b1, b2, steps, out);
}

// round 15
// speedup vs baseline: 1.0357x; 1.0357x over previous
#include <cuda_runtime.h>
#include <cuda_fp16.h>
#include <mma.h>
#include <cstdint>

using namespace nvcuda;

typedef unsigned long long u64;

// ---------------- packed f32x2 helpers ----------------
__device__ __forceinline__ u64 pk2(float a, float b) {
    u64 r; asm("mov.b64 %0, {%1,%2};" : "=l"(r) : "f"(a), "f"(b)); return r;
}
__device__ __forceinline__ void upk2(u64 v, float& a, float& b) {
    asm("mov.b64 {%0,%1}, %2;" : "=f"(a), "=f"(b) : "l"(v));
}
__device__ __forceinline__ u64 ffma2(u64 a, u64 b, u64 c) {
    u64 d; asm("fma.rn.f32x2 %0, %1, %2, %3;" : "=l"(d) : "l"(a), "l"(b), "l"(c)); return d;
}
__device__ __forceinline__ u64 fmul2(u64 a, u64 b) {
    u64 d; asm("mul.rn.f32x2 %0, %1, %2;" : "=l"(d) : "l"(a), "l"(b)); return d;
}
__device__ __forceinline__ u64 fadd2(u64 a, u64 b) {
    u64 d; asm("add.rn.f32x2 %0, %1, %2;" : "=l"(d) : "l"(a), "l"(b)); return d;
}
__device__ __forceinline__ float tanh_(float x) {
    float t; asm("tanh.approx.f32 %0, %1;" : "=f"(t) : "f"(x)); return t;
}

#define H     1024
#define DIN   784
#define DOUT  10
#define MAXB  16384
#define KPAD2 800          // 25 * 32; zero padding beyond 784
#define NI    25           // GEMM outer iterations (K-step 32)

__device__ float g_xW1[(size_t)MAXB * H];                        // x @ W1 (fp32)
__device__ __align__(16) __half g_xh[(size_t)MAXB * KPAD2];      // x  fp16 [m][k], zero-pad
__device__ __align__(16) __half g_w1h[(size_t)KPAD2 * H];        // W1 fp16 [k][n], zero-pad

// ==================== merged conv kernel, vectorized (one-time) ====================
// DIN = 784 = 98 * 8, so every 8-elem unit is fully in-range or fully padding:
// guard hoisted to unit level -> 2x LDG.128 fast path, no scalarization.
__global__ __launch_bounds__(256) void conv_all(const float* __restrict__ x,
                                                const float* __restrict__ W1, int B) {
    int u = blockIdx.x * 256 + threadIdx.x;
    const int xunits = B * (KPAD2 / 8);
    const int wunits = KPAD2 * (H / 8);
    if (u < xunits) {
        int m = u / (KPAD2 / 8), k = (u - m * (KPAD2 / 8)) * 8;
        ushort4 lo = {0, 0, 0, 0}, hi = {0, 0, 0, 0};
        if (k < DIN) {                                   // full unit (784 % 8 == 0)
            float4 v0 = *(const float4*)(x + (size_t)m * DIN + k);
            float4 v1 = *(const float4*)(x + (size_t)m * DIN + k + 4);
            lo = make_ushort4(__half_as_ushort(__float2half_rn(v0.x)),
                              __half_as_ushort(__float2half_rn(v0.y)),
                              __half_as_ushort(__float2half_rn(v0.z)),
                              __half_as_ushort(__float2half_rn(v0.w)));
            hi = make_ushort4(__half_as_ushort(__float2half_rn(v1.x)),
                              __half_as_ushort(__float2half_rn(v1.y)),
                              __half_as_ushort(__float2half_rn(v1.z)),
                              __half_as_ushort(__float2half_rn(v1.w)));
        }
        *(ushort4*)(g_xh + (size_t)m * KPAD2 + k)     = lo;
        *(ushort4*)(g_xh + (size_t)m * KPAD2 + k + 4) = hi;
    } else if (u < xunits + wunits) {
        int v = u - xunits;
        int k = v / (H / 8), n = (v - k * (H / 8)) * 8;
        ushort4 lo = {0, 0, 0, 0}, hi = {0, 0, 0, 0};
        if (k < DIN) {
            float4 v0 = *(const float4*)(W1 + (size_t)k * H + n);
            float4 v1 = *(const float4*)(W1 + (size_t)k * H + n + 4);
            lo = make_ushort4(__half_as_ushort(__float2half_rn(v0.x)),
                              __half_as_ushort(__float2half_rn(v0.y)),
                              __half_as_ushort(__float2half_rn(v0.z)),
                              __half_as_ushort(__float2half_rn(v0.w)));
            hi = make_ushort4(__half_as_ushort(__float2half_rn(v1.x)),
                              __half_as_ushort(__float2half_rn(v1.y)),
                              __half_as_ushort(__float2half_rn(v1.z)),
                              __half_as_ushort(__float2half_rn(v1.w)));
        }
        *(ushort4*)(g_w1h + (size_t)k * H + n)     = lo;
        *(ushort4*)(g_w1h + (size_t)k * H + n + 4) = hi;
    }
}

// ==================== fp16 MMA GEMM, K-step 32, cp.async, 2-stage (R13 exact) ====================
#define ASTR 40
#define BSTR2 136

__device__ __forceinline__ void cp16(uint32_t dst, const void* src) {
    asm volatile("cp.async.cg.shared.global [%0], [%1], 16;" :: "r"(dst), "l"(src));
}

__global__ __launch_bounds__(256, 2) void mma_xw1() {
    __shared__ __half sA[2][128 * ASTR];    // 20.5 KB
    __shared__ __half sB[2][32 * BSTR2];    // 17.4 KB

    const int tid  = threadIdx.x;
    const int warp = tid >> 5;
    const int m0 = blockIdx.y * 128;
    const int n0 = blockIdx.x * 128;
    const int wm = (warp >> 2) * 64;
    const int wn = (warp & 3) * 32;

    wmma::fragment<wmma::accumulator, 16, 16, 16, float> acc[4][2];
#pragma unroll
    for (int i = 0; i < 4; ++i)
#pragma unroll
        for (int j = 0; j < 2; ++j) wmma::fill_fragment(acc[i][j], 0.0f);

    const int arow = tid >> 1, ak = (tid & 1) * 16;
    const __half* asrc = g_xh + (size_t)(m0 + arow) * KPAD2 + ak;
    const int aoff = arow * ASTR + ak;
    const int bkr = tid >> 3, bnc = (tid & 7) * 16;
    const __half* bsrc = g_w1h + (size_t)bkr * H + n0 + bnc;
    const int boff = bkr * BSTR2 + bnc;

    auto cpAB = [&](int it, int s) {
        cp16((uint32_t)__cvta_generic_to_shared(&sA[s][aoff]),     asrc + it * 32);
        cp16((uint32_t)__cvta_generic_to_shared(&sA[s][aoff + 8]), asrc + it * 32 + 8);
        cp16((uint32_t)__cvta_generic_to_shared(&sB[s][boff]),     bsrc + (size_t)it * 32 * H);
        cp16((uint32_t)__cvta_generic_to_shared(&sB[s][boff + 8]), bsrc + (size_t)it * 32 * H + 8);
        asm volatile("cp.async.commit_group;" ::: "memory");
    };

    cpAB(0, 0);

    for (int it = 0; it < NI; ++it) {
        asm volatile("cp.async.wait_group 0;" ::: "memory");
        __syncthreads();
        if (it + 1 < NI) cpAB(it + 1, (it + 1) & 1);

        const int s = it & 1;
#pragma unroll
        for (int ks = 0; ks < 32; ks += 16) {
            wmma::fragment<wmma::matrix_b, 16, 16, 16, __half, wmma::row_major> bf[2];
#pragma unroll
            for (int j = 0; j < 2; ++j)
                wmma::load_matrix_sync(bf[j], &sB[s][ks * BSTR2 + wn + j * 16], BSTR2);
#pragma unroll
            for (int i = 0; i < 4; ++i) {
                wmma::fragment<wmma::matrix_a, 16, 16, 16, __half, wmma::row_major> af;
                wmma::load_matrix_sync(af, &sA[s][(wm + i * 16) * ASTR + ks], ASTR);
#pragma unroll
                for (int j = 0; j < 2; ++j)
                    wmma::mma_sync(acc[i][j], af, bf[j], acc[i][j]);
            }
        }
    }

#pragma unroll
    for (int i = 0; i < 4; ++i)
#pragma unroll
        for (int j = 0; j < 2; ++j) {
            float* C = g_xW1 + (size_t)(m0 + wm + i * 16) * H + (n0 + wn + j * 16);
            wmma::store_matrix_sync(C, acc[i][j], H, wmma::mem_row_major);
        }
}

// ==================== Kernel 2: 50-step settle (R5 verbatim — frozen) ====================
__global__ __launch_bounds__(256, 2) void settle_kernel(
    const float* __restrict__ u1g, const float* __restrict__ u2g,
    const float* __restrict__ W2g, const float* __restrict__ b1g,
    const float* __restrict__ b2g, const int* __restrict__ steps_p,
    float* __restrict__ outg)
{
    __shared__ float c1_s[4 * H];
    __shared__ __align__(16) float r2_s[4][12];
    __shared__ u64 wpart[80 * 33];

    const int tid  = threadIdx.x;
    const int lane = tid & 31;
    const int wid  = tid >> 5;
    const int b0   = blockIdx.x * 4;
    const int nsteps = *steps_p;

    u64 w2p[4][5];
#pragma unroll
    for (int j = 0; j < 4; ++j) {
        const float* w = W2g + (tid + 256 * j) * DOUT;
#pragma unroll
        for (int k = 0; k < 5; ++k)
            w2p[j][k] = pk2(w[2 * k] * 0.0625f, w[2 * k + 1] * 0.0625f);
    }

    float u1v[4][4];
#pragma unroll
    for (int r = 0; r < 4; ++r)
#pragma unroll
        for (int j = 0; j < 4; ++j)
            u1v[r][j] = 0.5f * u1g[(size_t)(b0 + r) * H + tid + 256 * j];

    {
        const float4* xs = (const float4*)(g_xW1 + (size_t)b0 * H);
        const float4* bs = (const float4*)b1g;
        float4* dst = (float4*)c1_s;
#pragma unroll
        for (int i = 0; i < 4; ++i) {
            int e = tid + 256 * i;
            float4 xv = xs[e];
            float4 bv = bs[e & 255];
            dst[e] = make_float4(fmaf(0.03125f, xv.x, 0.0625f * bv.x),
                                 fmaf(0.03125f, xv.y, 0.0625f * bv.y),
                                 fmaf(0.03125f, xv.z, 0.0625f * bv.z),
                                 fmaf(0.03125f, xv.w, 0.0625f * bv.w));
        }
    }

    const bool pb = tid < 160;
    const int r_b  = tid / 40;
    const int rem  = tid - 40 * r_b;
    const int o_b  = rem >> 2;
    const int q4   = rem & 3;
    const int k_b  = o_b >> 1;
    const int half = o_b & 1;
    const float* fb = (const float*)(wpart + ((size_t)((r_b * 5 + k_b) * 4 + q4)) * 33);
    const float* fb_pre = (const float*)(wpart + ((size_t)(k_b * 4 + q4)) * 33);

    {
        u64 qa[5];
#pragma unroll
        for (int k = 0; k < 5; ++k)
            qa[k] = fadd2(fadd2(w2p[0][k], w2p[1][k]), fadd2(w2p[2][k], w2p[3][k]));
#pragma unroll
        for (int k = 0; k < 5; ++k)
            qa[k] = fadd2(qa[k], __shfl_xor_sync(0xffffffffu, qa[k], 16));
        if (lane < 16) {
            int pIdx = wid * 16 + lane;
            int chunk = pIdx >> 5, pos = pIdx & 31;
#pragma unroll
            for (int k = 0; k < 5; ++k)
                wpart[(k * 4 + chunk) * 33 + pos] = qa[k];
        }
    }
    __syncthreads();

    float C2v = 0.0f, wv = 0.0f, r2v = 0.0f;
    if (pb) {
        float s0a = 0, s0b = 0, s1a = 0, s1b = 0;
#pragma unroll
        for (int i = 0; i < 16; ++i) {
            float2 za = *(const float2*)(fb_pre + 4 * i);
            float2 zb = *(const float2*)(fb_pre + 4 * i + 2);
            s0a += za.x; s1a += za.y; s0b += zb.x; s1b += zb.y;
        }
        float s = half ? (s1a + s1b) : (s0a + s0b);
        s += __shfl_xor_sync(0xffffffffu, s, 1);
        s += __shfl_xor_sync(0xffffffffu, s, 2);
        C2v = fmaf(8.0f, s, b2g[o_b]);
        wv  = 0.5f * u2g[(b0 + r_b) * DOUT + o_b];
        float tau = tanh_(wv);
        r2v = fmaf(0.5f, tau, 0.5f);
        if (q4 == 0) r2_s[r_b][o_b] = r2v;
    }
    __syncthreads();

    for (int s = 0; s < nsteps; ++s) {
#pragma unroll
        for (int r = 0; r < 4; ++r) {
            ulonglong2 ra = *(const ulonglong2*)&r2_s[r][0];
            ulonglong2 rb = *(const ulonglong2*)&r2_s[r][4];
            u64 rc = *(const u64*)&r2_s[r][8];
            u64 r2p[5] = {ra.x, ra.y, rb.x, rb.y, rc};
            u64 qacc[5] = {0ULL, 0ULL, 0ULL, 0ULL, 0ULL};
#pragma unroll
            for (int j = 0; j < 4; ++j) {
                float v  = u1v[r][j];
                float th = tanh_(v);
                u64 p2 = fmul2(w2p[j][0], r2p[0]);
                p2 = ffma2(w2p[j][1], r2p[1], p2);
                p2 = ffma2(w2p[j][2], r2p[2], p2);
                p2 = ffma2(w2p[j][3], r2p[3], p2);
                p2 = ffma2(w2p[j][4], r2p[4], p2);
                float pa, pb2; upk2(p2, pa, pb2);
                u64 th2 = pk2(th, th);
#pragma unroll
                for (int k = 0; k < 5; ++k) qacc[k] = ffma2(th2, w2p[j][k], qacc[k]);
                float t   = (pa + pb2) + c1_s[r * H + tid + 256 * j];
                float omt = fmaf(-th, th, 1.0f);
                u1v[r][j] = fmaf(omt, t, 0.5f * v);
            }
#pragma unroll
            for (int k = 0; k < 5; ++k)
                qacc[k] = fadd2(qacc[k], __shfl_xor_sync(0xffffffffu, qacc[k], 16));
            if (lane < 16) {
                int pIdx = wid * 16 + lane;
                int chunk = pIdx >> 5, pos = pIdx & 31;
#pragma unroll
                for (int k = 0; k < 5; ++k)
                    wpart[((r * 5 + k) * 4 + chunk) * 33 + pos] = qacc[k];
            }
        }
        __syncthreads();

        if (pb) {
            float s0a = 0, s0b = 0, s1a = 0, s1b = 0;
#pragma unroll
            for (int i = 0; i < 16; ++i) {
                float2 za = *(const float2*)(fb + 4 * i);
                float2 zb = *(const float2*)(fb + 4 * i + 2);
                s0a += za.x; s1a += za.y; s0b += zb.x; s1b += zb.y;
            }
            float sv = half ? (s1a + s1b) : (s0a + s0b);
            sv += __shfl_xor_sync(0xffffffffu, sv, 1);
            sv += __shfl_xor_sync(0xffffffffu, sv, 2);
            float gq  = fmaf(8.0f, sv, C2v);
            float tau = tanh_(wv);
            float om  = fmaf(-tau, tau, 1.0f);
            wv = fmaf(0.0625f * om, gq, 0.5f * wv);
            r2v = fmaf(0.5f, tanh_(wv), 0.5f);
            if (q4 == 0) r2_s[r_b][o_b] = r2v;
        }
        __syncthreads();
    }

    if (pb && q4 == 0)
        outg[(b0 + r_b) * DOUT + o_b] = r2v;
}

// ==================== launch ====================
extern "C" void kernel_launch(void* const* d_in, const int* in_sizes, int n_in,
                              void* d_out, int out_size) {
    const float* x     = (const float*)d_in[0];
    const float* u1    = (const float*)d_in[1];
    const float* u2    = (const float*)d_in[2];
    const float* W1    = (const float*)d_in[3];
    const float* W2    = (const float*)d_in[4];
    const float* b1    = (const float*)d_in[5];
    const float* b2    = (const float*)d_in[6];
    const int*   steps = (const int*)d_in[7];
    float* out = (float*)d_out;

    const int B = in_sizes[1] / H;

    const int cunits = B * (KPAD2 / 8) + KPAD2 * (H / 8);
    conv_all<<<(cunits + 255) / 256, 256>>>(x, W1, B);
    mma_xw1<<<dim3(H / 128, B / 128), 256>>>();
    settle_kernel<<<B / 4, 256>>>(u1, u2, W2, b1, b2, steps, out);
}

// round 16
// speedup vs baseline: 1.0386x; 1.0028x over previous
#include <cuda_runtime.h>
#include <cuda_fp16.h>
#include <mma.h>
#include <cstdint>

using namespace nvcuda;

typedef unsigned long long u64;

// ---------------- packed f32x2 helpers ----------------
__device__ __forceinline__ u64 pk2(float a, float b) {
    u64 r; asm("mov.b64 %0, {%1,%2};" : "=l"(r) : "f"(a), "f"(b)); return r;
}
__device__ __forceinline__ void upk2(u64 v, float& a, float& b) {
    asm("mov.b64 {%0,%1}, %2;" : "=f"(a), "=f"(b) : "l"(v));
}
__device__ __forceinline__ u64 ffma2(u64 a, u64 b, u64 c) {
    u64 d; asm("fma.rn.f32x2 %0, %1, %2, %3;" : "=l"(d) : "l"(a), "l"(b), "l"(c)); return d;
}
__device__ __forceinline__ u64 fmul2(u64 a, u64 b) {
    u64 d; asm("mul.rn.f32x2 %0, %1, %2;" : "=l"(d) : "l"(a), "l"(b)); return d;
}
__device__ __forceinline__ u64 fadd2(u64 a, u64 b) {
    u64 d; asm("add.rn.f32x2 %0, %1, %2;" : "=l"(d) : "l"(a), "l"(b)); return d;
}
__device__ __forceinline__ float tanh_(float x) {
    float t; asm("tanh.approx.f32 %0, %1;" : "=f"(t) : "f"(x)); return t;
}

#define H     1024
#define DIN   784
#define DOUT  10
#define MAXB  16384
#define KPAD2 800          // 25 * 32; zero padding beyond 784
#define NI    25           // GEMM outer iterations (K-step 32)

__device__ float g_xW1[(size_t)MAXB * H];                        // x @ W1 (fp32)
__device__ __align__(16) __half g_xh[(size_t)MAXB * KPAD2];      // x  fp16 [m][k], zero-pad
__device__ __align__(16) __half g_w1h[(size_t)KPAD2 * H];        // W1 fp16 [k][n], zero-pad

// ==================== merged conv kernel, vectorized (R15 exact) ====================
__global__ __launch_bounds__(256) void conv_all(const float* __restrict__ x,
                                                const float* __restrict__ W1, int B) {
    int u = blockIdx.x * 256 + threadIdx.x;
    const int xunits = B * (KPAD2 / 8);
    const int wunits = KPAD2 * (H / 8);
    if (u < xunits) {
        int m = u / (KPAD2 / 8), k = (u - m * (KPAD2 / 8)) * 8;
        ushort4 lo = {0, 0, 0, 0}, hi = {0, 0, 0, 0};
        if (k < DIN) {
            float4 v0 = *(const float4*)(x + (size_t)m * DIN + k);
            float4 v1 = *(const float4*)(x + (size_t)m * DIN + k + 4);
            lo = make_ushort4(__half_as_ushort(__float2half_rn(v0.x)),
                              __half_as_ushort(__float2half_rn(v0.y)),
                              __half_as_ushort(__float2half_rn(v0.z)),
                              __half_as_ushort(__float2half_rn(v0.w)));
            hi = make_ushort4(__half_as_ushort(__float2half_rn(v1.x)),
                              __half_as_ushort(__float2half_rn(v1.y)),
                              __half_as_ushort(__float2half_rn(v1.z)),
                              __half_as_ushort(__float2half_rn(v1.w)));
        }
        *(ushort4*)(g_xh + (size_t)m * KPAD2 + k)     = lo;
        *(ushort4*)(g_xh + (size_t)m * KPAD2 + k + 4) = hi;
    } else if (u < xunits + wunits) {
        int v = u - xunits;
        int k = v / (H / 8), n = (v - k * (H / 8)) * 8;
        ushort4 lo = {0, 0, 0, 0}, hi = {0, 0, 0, 0};
        if (k < DIN) {
            float4 v0 = *(const float4*)(W1 + (size_t)k * H + n);
            float4 v1 = *(const float4*)(W1 + (size_t)k * H + n + 4);
            lo = make_ushort4(__half_as_ushort(__float2half_rn(v0.x)),
                              __half_as_ushort(__float2half_rn(v0.y)),
                              __half_as_ushort(__float2half_rn(v0.z)),
                              __half_as_ushort(__float2half_rn(v0.w)));
            hi = make_ushort4(__half_as_ushort(__float2half_rn(v1.x)),
                              __half_as_ushort(__float2half_rn(v1.y)),
                              __half_as_ushort(__float2half_rn(v1.z)),
                              __half_as_ushort(__float2half_rn(v1.w)));
        }
        *(ushort4*)(g_w1h + (size_t)k * H + n)     = lo;
        *(ushort4*)(g_w1h + (size_t)k * H + n + 4) = hi;
    }
}

// ==================== fp16 MMA GEMM, K-step 32, cp.async 3-STAGE ring ====================
// Only change this round: 3-stage ring + wait_group 1 keeps one cp.async group
// in flight through each compute body (2-stage drained fully every iter).
// Dynamic smem 56.8 KB; still 2 CTAs/SM. Accumulation order unchanged.
#define ASTR 40
#define BSTR2 136
#define ATILE (128 * ASTR)
#define BTILE (32 * BSTR2)
#define MMA3_BYTES (3 * (ATILE + BTILE) * 2)   // 56832

__device__ __forceinline__ void cp16(uint32_t dst, const void* src) {
    asm volatile("cp.async.cg.shared.global [%0], [%1], 16;" :: "r"(dst), "l"(src));
}

__global__ __launch_bounds__(256, 2) void mma_xw1() {
    extern __shared__ __half gsm[];
    __half* sA = gsm;                 // [3][ATILE]
    __half* sB = gsm + 3 * ATILE;     // [3][BTILE]

    const int tid  = threadIdx.x;
    const int warp = tid >> 5;
    const int m0 = blockIdx.y * 128;
    const int n0 = blockIdx.x * 128;
    const int wm = (warp >> 2) * 64;
    const int wn = (warp & 3) * 32;

    wmma::fragment<wmma::accumulator, 16, 16, 16, float> acc[4][2];
#pragma unroll
    for (int i = 0; i < 4; ++i)
#pragma unroll
        for (int j = 0; j < 2; ++j) wmma::fill_fragment(acc[i][j], 0.0f);

    const int arow = tid >> 1, ak = (tid & 1) * 16;
    const __half* asrc = g_xh + (size_t)(m0 + arow) * KPAD2 + ak;
    const int aoff = arow * ASTR + ak;
    const int bkr = tid >> 3, bnc = (tid & 7) * 16;
    const __half* bsrc = g_w1h + (size_t)bkr * H + n0 + bnc;
    const int boff = bkr * BSTR2 + bnc;

    auto cpAB = [&](int it, int s) {
        __half* a = sA + s * ATILE;
        __half* b = sB + s * BTILE;
        cp16((uint32_t)__cvta_generic_to_shared(a + aoff),     asrc + it * 32);
        cp16((uint32_t)__cvta_generic_to_shared(a + aoff + 8), asrc + it * 32 + 8);
        cp16((uint32_t)__cvta_generic_to_shared(b + boff),     bsrc + (size_t)it * 32 * H);
        cp16((uint32_t)__cvta_generic_to_shared(b + boff + 8), bsrc + (size_t)it * 32 * H + 8);
        asm volatile("cp.async.commit_group;" ::: "memory");
    };

    cpAB(0, 0);
    cpAB(1, 1);

    for (int it = 0; it < NI; ++it) {
        if (it + 1 < NI) { asm volatile("cp.async.wait_group 1;" ::: "memory"); }
        else             { asm volatile("cp.async.wait_group 0;" ::: "memory"); }
        __syncthreads();                   // stage it%3 full; stage (it+2)%3 reads done
        if (it + 2 < NI) cpAB(it + 2, (it + 2) % 3);

        const int s = it % 3;
        const __half* a = sA + s * ATILE;
        const __half* b = sB + s * BTILE;
#pragma unroll
        for (int ks = 0; ks < 32; ks += 16) {
            wmma::fragment<wmma::matrix_b, 16, 16, 16, __half, wmma::row_major> bf[2];
#pragma unroll
            for (int j = 0; j < 2; ++j)
                wmma::load_matrix_sync(bf[j], &b[ks * BSTR2 + wn + j * 16], BSTR2);
#pragma unroll
            for (int i = 0; i < 4; ++i) {
                wmma::fragment<wmma::matrix_a, 16, 16, 16, __half, wmma::row_major> af;
                wmma::load_matrix_sync(af, &a[(wm + i * 16) * ASTR + ks], ASTR);
#pragma unroll
                for (int j = 0; j < 2; ++j)
                    wmma::mma_sync(acc[i][j], af, bf[j], acc[i][j]);
            }
        }
    }

#pragma unroll
    for (int i = 0; i < 4; ++i)
#pragma unroll
        for (int j = 0; j < 2; ++j) {
            float* C = g_xW1 + (size_t)(m0 + wm + i * 16) * H + (n0 + wn + j * 16);
            wmma::store_matrix_sync(C, acc[i][j], H, wmma::mem_row_major);
        }
}

// ==================== Kernel 2: 50-step settle (R5 verbatim — frozen) ====================
__global__ __launch_bounds__(256, 2) void settle_kernel(
    const float* __restrict__ u1g, const float* __restrict__ u2g,
    const float* __restrict__ W2g, const float* __restrict__ b1g,
    const float* __restrict__ b2g, const int* __restrict__ steps_p,
    float* __restrict__ outg)
{
    __shared__ float c1_s[4 * H];
    __shared__ __align__(16) float r2_s[4][12];
    __shared__ u64 wpart[80 * 33];

    const int tid  = threadIdx.x;
    const int lane = tid & 31;
    const int wid  = tid >> 5;
    const int b0   = blockIdx.x * 4;
    const int nsteps = *steps_p;

    u64 w2p[4][5];
#pragma unroll
    for (int j = 0; j < 4; ++j) {
        const float* w = W2g + (tid + 256 * j) * DOUT;
#pragma unroll
        for (int k = 0; k < 5; ++k)
            w2p[j][k] = pk2(w[2 * k] * 0.0625f, w[2 * k + 1] * 0.0625f);
    }

    float u1v[4][4];
#pragma unroll
    for (int r = 0; r < 4; ++r)
#pragma unroll
        for (int j = 0; j < 4; ++j)
            u1v[r][j] = 0.5f * u1g[(size_t)(b0 + r) * H + tid + 256 * j];

    {
        const float4* xs = (const float4*)(g_xW1 + (size_t)b0 * H);
        const float4* bs = (const float4*)b1g;
        float4* dst = (float4*)c1_s;
#pragma unroll
        for (int i = 0; i < 4; ++i) {
            int e = tid + 256 * i;
            float4 xv = xs[e];
            float4 bv = bs[e & 255];
            dst[e] = make_float4(fmaf(0.03125f, xv.x, 0.0625f * bv.x),
                                 fmaf(0.03125f, xv.y, 0.0625f * bv.y),
                                 fmaf(0.03125f, xv.z, 0.0625f * bv.z),
                                 fmaf(0.03125f, xv.w, 0.0625f * bv.w));
        }
    }

    const bool pb = tid < 160;
    const int r_b  = tid / 40;
    const int rem  = tid - 40 * r_b;
    const int o_b  = rem >> 2;
    const int q4   = rem & 3;
    const int k_b  = o_b >> 1;
    const int half = o_b & 1;
    const float* fb = (const float*)(wpart + ((size_t)((r_b * 5 + k_b) * 4 + q4)) * 33);
    const float* fb_pre = (const float*)(wpart + ((size_t)(k_b * 4 + q4)) * 33);

    {
        u64 qa[5];
#pragma unroll
        for (int k = 0; k < 5; ++k)
            qa[k] = fadd2(fadd2(w2p[0][k], w2p[1][k]), fadd2(w2p[2][k], w2p[3][k]));
#pragma unroll
        for (int k = 0; k < 5; ++k)
            qa[k] = fadd2(qa[k], __shfl_xor_sync(0xffffffffu, qa[k], 16));
        if (lane < 16) {
            int pIdx = wid * 16 + lane;
            int chunk = pIdx >> 5, pos = pIdx & 31;
#pragma unroll
            for (int k = 0; k < 5; ++k)
                wpart[(k * 4 + chunk) * 33 + pos] = qa[k];
        }
    }
    __syncthreads();

    float C2v = 0.0f, wv = 0.0f, r2v = 0.0f;
    if (pb) {
        float s0a = 0, s0b = 0, s1a = 0, s1b = 0;
#pragma unroll
        for (int i = 0; i < 16; ++i) {
            float2 za = *(const float2*)(fb_pre + 4 * i);
            float2 zb = *(const float2*)(fb_pre + 4 * i + 2);
            s0a += za.x; s1a += za.y; s0b += zb.x; s1b += zb.y;
        }
        float s = half ? (s1a + s1b) : (s0a + s0b);
        s += __shfl_xor_sync(0xffffffffu, s, 1);
        s += __shfl_xor_sync(0xffffffffu, s, 2);
        C2v = fmaf(8.0f, s, b2g[o_b]);
        wv  = 0.5f * u2g[(b0 + r_b) * DOUT + o_b];
        float tau = tanh_(wv);
        r2v = fmaf(0.5f, tau, 0.5f);
        if (q4 == 0) r2_s[r_b][o_b] = r2v;
    }
    __syncthreads();

    for (int s = 0; s < nsteps; ++s) {
#pragma unroll
        for (int r = 0; r < 4; ++r) {
            ulonglong2 ra = *(const ulonglong2*)&r2_s[r][0];
            ulonglong2 rb = *(const ulonglong2*)&r2_s[r][4];
            u64 rc = *(const u64*)&r2_s[r][8];
            u64 r2p[5] = {ra.x, ra.y, rb.x, rb.y, rc};
            u64 qacc[5] = {0ULL, 0ULL, 0ULL, 0ULL, 0ULL};
#pragma unroll
            for (int j = 0; j < 4; ++j) {
                float v  = u1v[r][j];
                float th = tanh_(v);
                u64 p2 = fmul2(w2p[j][0], r2p[0]);
                p2 = ffma2(w2p[j][1], r2p[1], p2);
                p2 = ffma2(w2p[j][2], r2p[2], p2);
                p2 = ffma2(w2p[j][3], r2p[3], p2);
                p2 = ffma2(w2p[j][4], r2p[4], p2);
                float pa, pb2; upk2(p2, pa, pb2);
                u64 th2 = pk2(th, th);
#pragma unroll
                for (int k = 0; k < 5; ++k) qacc[k] = ffma2(th2, w2p[j][k], qacc[k]);
                float t   = (pa + pb2) + c1_s[r * H + tid + 256 * j];
                float omt = fmaf(-th, th, 1.0f);
                u1v[r][j] = fmaf(omt, t, 0.5f * v);
            }
#pragma unroll
            for (int k = 0; k < 5; ++k)
                qacc[k] = fadd2(qacc[k], __shfl_xor_sync(0xffffffffu, qacc[k], 16));
            if (lane < 16) {
                int pIdx = wid * 16 + lane;
                int chunk = pIdx >> 5, pos = pIdx & 31;
#pragma unroll
                for (int k = 0; k < 5; ++k)
                    wpart[((r * 5 + k) * 4 + chunk) * 33 + pos] = qacc[k];
            }
        }
        __syncthreads();

        if (pb) {
            float s0a = 0, s0b = 0, s1a = 0, s1b = 0;
#pragma unroll
            for (int i = 0; i < 16; ++i) {
                float2 za = *(const float2*)(fb + 4 * i);
                float2 zb = *(const float2*)(fb + 4 * i + 2);
                s0a += za.x; s1a += za.y; s0b += zb.x; s1b += zb.y;
            }
            float sv = half ? (s1a + s1b) : (s0a + s0b);
            sv += __shfl_xor_sync(0xffffffffu, sv, 1);
            sv += __shfl_xor_sync(0xffffffffu, sv, 2);
            float gq  = fmaf(8.0f, sv, C2v);
            float tau = tanh_(wv);
            float om  = fmaf(-tau, tau, 1.0f);
            wv = fmaf(0.0625f * om, gq, 0.5f * wv);
            r2v = fmaf(0.5f, tanh_(wv), 0.5f);
            if (q4 == 0) r2_s[r_b][o_b] = r2v;
        }
        __syncthreads();
    }

    if (pb && q4 == 0)
        outg[(b0 + r_b) * DOUT + o_b] = r2v;
}

// ==================== launch ====================
extern "C" void kernel_launch(void* const* d_in, const int* in_sizes, int n_in,
                              void* d_out, int out_size) {
    const float* x     = (const float*)d_in[0];
    const float* u1    = (const float*)d_in[1];
    const float* u2    = (const float*)d_in[2];
    const float* W1    = (const float*)d_in[3];
    const float* W2    = (const float*)d_in[4];
    const float* b1    = (const float*)d_in[5];
    const float* b2    = (const float*)d_in[6];
    const int*   steps = (const int*)d_in[7];
    float* out = (float*)d_out;

    const int B = in_sizes[1] / H;

    cudaFuncSetAttribute(mma_xw1, cudaFuncAttributeMaxDynamicSharedMemorySize,
                         MMA3_BYTES);

    const int cunits = B * (KPAD2 / 8) + KPAD2 * (H / 8);
    conv_all<<<(cunits + 255) / 256, 256>>>(x, W1, B);
    mma_xw1<<<dim3(H / 128, B / 128), 256, MMA3_BYTES>>>();
    settle_kernel<<<B / 4, 256>>>(u1, u2, W2, b1, b2, steps, out);
}